// round 6
// baseline (speedup 1.0000x reference)
#include <cuda_runtime.h>
#include <cuda_bf16.h>
#include <cstdint>
#include <math.h>

#define B_  4
#define S_  4096
#define D_  64
#define BQ  128
#define BK  128
#define QT_PER_B   32
#define UNITS_PER_B 528
#define NUNITS     2112

/* ---------------- scratch ---------------- */
__device__ float g_Lp[(size_t)NUNITS * 128];
__device__ float g_Op[(size_t)NUNITS * 128 * 64];
__device__ float g_invL[B_ * S_];

/* ---------------- SMEM map (bytes) ---------------- */
#define QK_STRIDE 72
#define EV_STRIDE 136
#define SM_RSUM   0                        /* 128*2 floats = 1024 B */
#define SM_QHI    1024
#define SM_QLO    (SM_QHI + 18432)
#define SM_KHI    (SM_QLO + 18432)
#define SM_KLO    (SM_KHI + 18432)
#define SM_VTHI   (SM_KLO + 18432)         /* 64*136*2 = 17408 */
#define SM_VTLO   (SM_VTHI + 17408)
#define SM_EHI    SM_QHI                   /* 128*136*2 = 34816, alias */
#define SM_ELO    (SM_QHI + 34816)
#define SMEM_TOTAL (SM_VTLO + 17408)       /* 109568 B -> 2 CTAs/SM */

#define MMA16816(c, a, b0, b1) \
    asm volatile("mma.sync.aligned.m16n8k16.row.col.f32.bf16.bf16.f32 " \
        "{%0,%1,%2,%3}, {%4,%5,%6,%7}, {%8,%9}, {%0,%1,%2,%3};"         \
        : "+f"((c)[0]), "+f"((c)[1]), "+f"((c)[2]), "+f"((c)[3])        \
        : "r"((a)[0]), "r"((a)[1]), "r"((a)[2]), "r"((a)[3]),           \
          "r"(b0), "r"(b1))

/* packed bf16 hi/lo split: (f0,f1) -> h2 (bf16x2), l2 (bf16x2 of residual) */
__device__ __forceinline__ void bf16_split2(float f0, float f1,
                                            uint32_t& h2, uint32_t& l2) {
    asm("cvt.rn.bf16x2.f32 %0, %1, %2;" : "=r"(h2) : "f"(f1), "f"(f0));
    float h0 = __uint_as_float(h2 << 16);
    float h1 = __uint_as_float(h2 & 0xFFFF0000u);
    float r0 = f0 - h0, r1 = f1 - h1;
    asm("cvt.rn.bf16x2.f32 %0, %1, %2;" : "=r"(l2) : "f"(r1), "f"(r0));
}

__device__ __forceinline__ float fast_exp(float x) {
    float t = x * 1.4426950408889634f;
    float r = t + 12582912.0f;
    int   n = __float_as_int(r) - 0x4B400000;
    float f = t - (r - 12582912.0f);
    float p = 1.3333558e-3f;
    p = fmaf(p, f, 9.6181291e-3f);
    p = fmaf(p, f, 5.5504109e-2f);
    p = fmaf(p, f, 2.4022651e-1f);
    p = fmaf(p, f, 6.9314718e-1f);
    p = fmaf(p, f, 1.0f);
    return __int_as_float(__float_as_int(p) + (n << 23));
}

/* ------------------------------------------------------------------ */
/* Kernel A: one (qt,kt) 128x128 unit per CTA; 512 thr, 16 warps.     */
/* ------------------------------------------------------------------ */
__global__ void __launch_bounds__(512, 2)
attn_tiles(const float* __restrict__ Q, const float* __restrict__ K,
           const float* __restrict__ V, float* __restrict__ outW,
           int writeW)
{
    extern __shared__ char smx[];

    const int tid = threadIdx.x;
    const int wid = tid >> 5;
    const int lid = tid & 31;
    const int g   = lid >> 2;   /* frag row     */
    const int tg  = lid & 3;    /* frag col pair */
    const int wr  = wid & 7;    /* 16-row block  */
    const int wc  = wid >> 3;   /* col half      */

    const int b = blockIdx.y;
    const int x = blockIdx.x;
    int qt = (int)((sqrtf(8.0f * (float)x + 1.0f) - 1.0f) * 0.5f);
    while ((qt + 1) * (qt + 2) / 2 <= x) qt++;
    while (qt * (qt + 1) / 2 > x) qt--;
    const int kt   = x - qt * (qt + 1) / 2;
    const int unit = b * UNITS_PER_B + x;
    const bool diag = (qt == kt);

    const float2* Qb = (const float2*)(Q + ((size_t)b * S_ + (size_t)qt * BQ) * D_);
    const float2* Kb = (const float2*)(K + ((size_t)b * S_ + (size_t)kt * BK) * D_);
    const float2* Vb = (const float2*)(V + ((size_t)b * S_ + (size_t)kt * BK) * D_);

    /* ---- load Q,K: split hi/lo bf16, row-major stride 72 ---- */
#pragma unroll
    for (int it = 0; it < 8; it++) {
        const int idx = tid + it * 512;
        const int row = idx >> 5, cp = idx & 31;
        const int soff = (row * QK_STRIDE + 2 * cp) * 2;
        {
            float2 v = Qb[idx];
            uint32_t h2, l2;
            bf16_split2(v.x, v.y, h2, l2);
            *(uint32_t*)(smx + SM_QHI + soff) = h2;
            *(uint32_t*)(smx + SM_QLO + soff) = l2;
        }
        {
            float2 v = Kb[idx];
            uint32_t h2, l2;
            bf16_split2(v.x, v.y, h2, l2);
            *(uint32_t*)(smx + SM_KHI + soff) = h2;
            *(uint32_t*)(smx + SM_KLO + soff) = l2;
        }
    }
    /* ---- V transpose -> Vt[d][k], stride 136 ---- */
#pragma unroll
    for (int it = 0; it < 8; it++) {
        const int idx = tid + it * 512;
        const int k = idx >> 5, dp = idx & 31;
        float2 v = Vb[idx];
#pragma unroll
        for (int s = 0; s < 2; s++) {
            const int d = 2 * dp + s;
            const float xv = s ? v.y : v.x;
            __nv_bfloat16 h = __float2bfloat16(xv);
            __nv_bfloat16 l = __float2bfloat16(xv - __bfloat162float(h));
            *(__nv_bfloat16*)(smx + SM_VTHI + (d * EV_STRIDE + k) * 2) = h;
            *(__nv_bfloat16*)(smx + SM_VTLO + (d * EV_STRIDE + k) * 2) = l;
        }
    }
    __syncthreads();

    /* ================= QK^T: warp tile 16 x 64 ================= */
    float c[8][4];
#pragma unroll
    for (int j = 0; j < 8; j++)
#pragma unroll
        for (int r = 0; r < 4; r++) c[j][r] = 0.0f;

#pragma unroll
    for (int p = 0; p < 3; p++) {
        const char* Ab = smx + ((p == 2) ? SM_QLO : SM_QHI);
        const char* Bb = smx + ((p == 1) ? SM_KLO : SM_KHI);
#pragma unroll
        for (int ks = 0; ks < 4; ks++) {
            uint32_t a[4];
            const int base = (16 * wr + g) * QK_STRIDE + 16 * ks + 2 * tg;
            a[0] = *(const uint32_t*)(Ab + 2 * base);
            a[1] = *(const uint32_t*)(Ab + 2 * (base + 8 * QK_STRIDE));
            a[2] = *(const uint32_t*)(Ab + 2 * (base + 8));
            a[3] = *(const uint32_t*)(Ab + 2 * (base + 8 * QK_STRIDE + 8));
#pragma unroll
            for (int j = 0; j < 8; j++) {
                const int cb = (64 * wc + 8 * j + g) * QK_STRIDE + 16 * ks + 2 * tg;
                uint32_t b0 = *(const uint32_t*)(Bb + 2 * cb);
                uint32_t b1 = *(const uint32_t*)(Bb + 2 * (cb + 8));
                MMA16816(c[j], a, b0, b1);
            }
        }
    }
    __syncthreads();   /* all Q/K smem reads done; E may overwrite */

    /* ======== epilogue: mask+exp, W store, E split, row sums ======== */
    float rs[2] = {0.0f, 0.0f};
#pragma unroll
    for (int u = 0; u < 2; u++) {
        const int row = 16 * wr + 8 * u + g;
        float* grow = outW + ((size_t)(b * S_ + qt * BQ + row)) * S_
                           + (size_t)kt * BK;
#pragma unroll
        for (int j = 0; j < 8; j++) {
            const int cb = 64 * wc + 8 * j + 2 * tg;
            float s0 = c[j][2 * u]     * 0.125f;
            float s1 = c[j][2 * u + 1] * 0.125f;
            float e0 = (diag && (cb     > row)) ? 0.0f : fast_exp(s0);
            float e1 = (diag && (cb + 1 > row)) ? 0.0f : fast_exp(s1);
            rs[u] += e0 + e1;
            if (writeW) {
                float2 w; w.x = e0; w.y = e1;
                *(float2*)(grow + cb) = w;
            }
            uint32_t h2, l2;
            bf16_split2(e0, e1, h2, l2);
            const int eoff = (row * EV_STRIDE + cb) * 2;
            *(uint32_t*)(smx + SM_EHI + eoff) = h2;
            *(uint32_t*)(smx + SM_ELO + eoff) = l2;
        }
    }
#pragma unroll
    for (int u = 0; u < 2; u++) {
        float v = rs[u];
        v += __shfl_xor_sync(0xffffffffu, v, 1);
        v += __shfl_xor_sync(0xffffffffu, v, 2);
        if (tg == 0) {
            const int row = 16 * wr + 8 * u + g;
            ((float*)(smx + SM_RSUM))[row * 2 + wc] = v;
        }
    }
    __syncthreads();

    if (tid < 128) {
        const float* r = (const float*)(smx + SM_RSUM);
        g_Lp[(size_t)unit * 128 + tid] = r[2 * tid] + r[2 * tid + 1];
    }

    /* ================= O = E @ V: warp tile 16 x 32 ================= */
    float o[4][4];
#pragma unroll
    for (int j = 0; j < 4; j++)
#pragma unroll
        for (int r = 0; r < 4; r++) o[j][r] = 0.0f;

#pragma unroll
    for (int p = 0; p < 3; p++) {
        const char* Ab = smx + ((p == 2) ? SM_ELO : SM_EHI);
        const char* Bb = smx + ((p == 1) ? SM_VTLO : SM_VTHI);
#pragma unroll
        for (int ks = 0; ks < 8; ks++) {
            uint32_t a[4];
            const int base = (16 * wr + g) * EV_STRIDE + 16 * ks + 2 * tg;
            a[0] = *(const uint32_t*)(Ab + 2 * base);
            a[1] = *(const uint32_t*)(Ab + 2 * (base + 8 * EV_STRIDE));
            a[2] = *(const uint32_t*)(Ab + 2 * (base + 8));
            a[3] = *(const uint32_t*)(Ab + 2 * (base + 8 * EV_STRIDE + 8));
#pragma unroll
            for (int j = 0; j < 4; j++) {
                const int cb = (32 * wc + 8 * j + g) * EV_STRIDE + 16 * ks + 2 * tg;
                uint32_t b0 = *(const uint32_t*)(Bb + 2 * cb);
                uint32_t b1 = *(const uint32_t*)(Bb + 2 * (cb + 8));
                MMA16816(o[j], a, b0, b1);
            }
        }
    }

    /* ---- store O partials ---- */
    float* Ob = g_Op + (size_t)unit * (128 * 64);
#pragma unroll
    for (int u = 0; u < 2; u++) {
        const int row = 16 * wr + 8 * u + g;
#pragma unroll
        for (int j = 0; j < 4; j++) {
            const int cb = 32 * wc + 8 * j + 2 * tg;
            float2 w;
            w.x = o[j][2 * u];
            w.y = o[j][2 * u + 1];
            *(float2*)(Ob + (size_t)row * 64 + cb) = w;
        }
    }
}

/* ---------------- Kernel B1: invL per row ---------------- */
__global__ void __launch_bounds__(256)
reduce_l()
{
    int t = blockIdx.x * 256 + threadIdx.x;
    if (t >= B_ * S_) return;
    int b = t >> 12, q = t & (S_ - 1);
    int qt = q >> 7, i = q & 127;
    int tri = qt * (qt + 1) / 2;
    float s = 0.0f;
    for (int kt = 0; kt <= qt; kt++)
        s += g_Lp[((size_t)(b * UNITS_PER_B + tri + kt)) * 128 + i];
    g_invL[t] = 1.0f / s;
}

/* ---------------- Kernel B2: O = (sum of partials) * invL ---------------- */
__global__ void __launch_bounds__(256)
reduce_o(float* __restrict__ outV)
{
    int t = blockIdx.x * 256 + threadIdx.x;
    if (t >= B_ * S_ * (D_ / 4)) return;
    int d4 = t & 15;
    int q  = (t >> 4) & (S_ - 1);
    int b  = t >> 16;
    int qt = q >> 7, i = q & 127;
    int tri = qt * (qt + 1) / 2;
    float ax = 0.f, ay = 0.f, az = 0.f, aw = 0.f;
    for (int kt = 0; kt <= qt; kt++) {
        const float4 v = *(const float4*)(g_Op +
            ((size_t)(b * UNITS_PER_B + tri + kt) * 128 + i) * 64 + d4 * 4);
        ax += v.x; ay += v.y; az += v.z; aw += v.w;
    }
    float inv = g_invL[b * S_ + q];
    float4 r; r.x = ax * inv; r.y = ay * inv; r.z = az * inv; r.w = aw * inv;
    *(float4*)(outV + ((size_t)(b * S_ + q)) * D_ + d4 * 4) = r;
}

/* ---------------- Kernel C: normalize weights + zero upper tiles -------- */
__global__ void __launch_bounds__(256)
norm_w(float* __restrict__ outW)
{
    size_t t = (size_t)blockIdx.x * 256 + threadIdx.x;   /* float4 index */
    int kq = (int)(t & 1023);
    int q  = (int)((t >> 10) & (S_ - 1));
    int b  = (int)(t >> 22);
    float4* p = (float4*)outW + t;
    int k = kq * 4;
    if ((k >> 7) > (q >> 7)) {
        float4 z; z.x = z.y = z.z = z.w = 0.0f;
        *p = z;
    } else {
        float inv = g_invL[b * S_ + q];
        float4 v = *p;
        v.x *= inv; v.y *= inv; v.z *= inv; v.w *= inv;
        *p = v;
    }
}

/* ------------------------------------------------------------------ */
extern "C" void kernel_launch(void* const* d_in, const int* in_sizes, int n_in,
                              void* d_out, int out_size)
{
    const float* Q = (const float*)d_in[0];
    const float* K = (const float*)d_in[1];
    const float* V = (const float*)d_in[2];

    const long long VE = (long long)B_ * S_ * D_;
    const long long WE = (long long)B_ * S_ * S_;

    float* outVec = nullptr;
    float* outW   = nullptr;
    int writeW = 0;
    if ((long long)out_size == VE + WE) {
        outVec = (float*)d_out;
        outW   = (float*)d_out + VE;
        writeW = 1;
    } else if ((long long)out_size == WE) {
        outW   = (float*)d_out;
        writeW = 1;
    } else {
        outVec = (float*)d_out;
    }
    float* wPtr = writeW ? outW : (float*)d_out;

    cudaFuncSetAttribute(attn_tiles, cudaFuncAttributeMaxDynamicSharedMemorySize,
                         SMEM_TOTAL);

    dim3 gA(UNITS_PER_B, B_);
    attn_tiles<<<gA, 512, SMEM_TOTAL>>>(Q, K, V, wPtr, writeW);

    reduce_l<<<(B_ * S_ + 255) / 256, 256>>>();

    if (outVec)
        reduce_o<<<(B_ * S_ * (D_ / 4) + 255) / 256, 256>>>(outVec);

    if (writeW) {
        long long nf4 = WE / 4;
        norm_w<<<(unsigned)(nf4 / 256), 256>>>(outW);
    }
}

// round 7
// speedup vs baseline: 1.3661x; 1.3661x over previous
#include <cuda_runtime.h>
#include <cuda_bf16.h>
#include <cstdint>
#include <math.h>

#define B_  4
#define S_  4096
#define D_  64
#define BQ  128
#define BK  128
#define QT_PER_B   32
#define UNITS_PER_B 528
#define NUNITS     2112

/* ---------------- scratch ---------------- */
__device__ float g_Lp[(size_t)NUNITS * 128];
__device__ float g_Op[(size_t)NUNITS * 128 * 64];
__device__ float g_invL[B_ * S_];

/* ---------------- SMEM map (bytes) ----------------
   Q/K tiles: [128][72 bf16]  (stride 72)
   Vt tiles : [64 d][138 bf16] (stride 138 -> conflict-free transpose STS)
   E tiles  : [128][138 bf16], aliases Q/K region                       */
#define QK_STRIDE 72
#define EV_STRIDE 138
#define SM_RSUM   0                        /* 128*2 floats = 1024 B */
#define SM_QHI    1024
#define SM_QLO    (SM_QHI + 18432)
#define SM_KHI    (SM_QLO + 18432)
#define SM_KLO    (SM_KHI + 18432)
#define SM_VTHI   (SM_KLO + 18432)         /* 64*138*2 = 17664 */
#define SM_VTLO   (SM_VTHI + 17664)
#define SM_EHI    SM_QHI                   /* 128*138*2 = 35328, alias */
#define SM_ELO    (SM_QHI + 35328)         /* fits inside 73728 Q/K region */
#define SMEM_TOTAL (SM_VTLO + 17664)       /* 110080 B -> 2 CTAs/SM */

#define MMA16816(c, a, b0, b1) \
    asm volatile("mma.sync.aligned.m16n8k16.row.col.f32.bf16.bf16.f32 " \
        "{%0,%1,%2,%3}, {%4,%5,%6,%7}, {%8,%9}, {%0,%1,%2,%3};"         \
        : "+f"((c)[0]), "+f"((c)[1]), "+f"((c)[2]), "+f"((c)[3])        \
        : "r"((a)[0]), "r"((a)[1]), "r"((a)[2]), "r"((a)[3]),           \
          "r"(b0), "r"(b1))

/* packed bf16 hi/lo split: (f0,f1) -> h2 (bf16x2), l2 (bf16x2 residual) */
__device__ __forceinline__ void bf16_split2(float f0, float f1,
                                            uint32_t& h2, uint32_t& l2) {
    asm("cvt.rn.bf16x2.f32 %0, %1, %2;" : "=r"(h2) : "f"(f1), "f"(f0));
    float h0 = __uint_as_float(h2 << 16);
    float h1 = __uint_as_float(h2 & 0xFFFF0000u);
    float r0 = f0 - h0, r1 = f1 - h1;
    asm("cvt.rn.bf16x2.f32 %0, %1, %2;" : "=r"(l2) : "f"(r1), "f"(r0));
}

__device__ __forceinline__ float fast_exp(float x) {
    float t = x * 1.4426950408889634f;
    float r = t + 12582912.0f;
    int   n = __float_as_int(r) - 0x4B400000;
    float f = t - (r - 12582912.0f);
    float p = 1.3333558e-3f;
    p = fmaf(p, f, 9.6181291e-3f);
    p = fmaf(p, f, 5.5504109e-2f);
    p = fmaf(p, f, 2.4022651e-1f);
    p = fmaf(p, f, 6.9314718e-1f);
    p = fmaf(p, f, 1.0f);
    return __int_as_float(__float_as_int(p) + (n << 23));
}

/* ------------------------------------------------------------------ */
/* Kernel A: one (qt,kt) 128x128 unit per CTA; 256 thr, HMMA 3-pass.  */
/* ------------------------------------------------------------------ */
__global__ void __launch_bounds__(256, 2)
attn_tiles(const float* __restrict__ Q, const float* __restrict__ K,
           const float* __restrict__ V, float* __restrict__ outW,
           int writeW)
{
    extern __shared__ char smx[];

    const int tid = threadIdx.x;
    const int wid = tid >> 5;
    const int lid = tid & 31;
    const int g   = lid >> 2;   /* frag row      */
    const int tg  = lid & 3;    /* frag col pair */
    const int wr  = wid & 3;    /* 32-row block  */
    const int wc  = wid >> 2;   /* col half      */

    const int b = blockIdx.y;
    const int x = blockIdx.x;
    int qt = (int)((sqrtf(8.0f * (float)x + 1.0f) - 1.0f) * 0.5f);
    while ((qt + 1) * (qt + 2) / 2 <= x) qt++;
    while (qt * (qt + 1) / 2 > x) qt--;
    const int kt   = x - qt * (qt + 1) / 2;
    const int unit = b * UNITS_PER_B + x;
    const bool diag = (qt == kt);

    const float2* Qb = (const float2*)(Q + ((size_t)b * S_ + (size_t)qt * BQ) * D_);
    const float2* Kb = (const float2*)(K + ((size_t)b * S_ + (size_t)kt * BK) * D_);
    const float*  Vs = V + ((size_t)b * S_ + (size_t)kt * BK) * D_;

    /* ---- load Q,K: split hi/lo bf16, row-major stride 72 ---- */
#pragma unroll
    for (int it = 0; it < 16; it++) {
        const int idx = tid + it * 256;
        const int row = idx >> 5, cp = idx & 31;
        const int soff = (row * QK_STRIDE + 2 * cp) * 2;
        {
            float2 v = Qb[idx];
            uint32_t h2, l2;
            bf16_split2(v.x, v.y, h2, l2);
            *(uint32_t*)(smx + SM_QHI + soff) = h2;
            *(uint32_t*)(smx + SM_QLO + soff) = l2;
        }
        {
            float2 v = Kb[idx];
            uint32_t h2, l2;
            bf16_split2(v.x, v.y, h2, l2);
            *(uint32_t*)(smx + SM_KHI + soff) = h2;
            *(uint32_t*)(smx + SM_KLO + soff) = l2;
        }
    }
    /* ---- V transpose: k-pair packed, conflict-free STS.32 ----
       item: (kp, d); load V[2kp][d], V[2kp+1][d]; store Vt[d][2kp..2kp+1] */
#pragma unroll
    for (int it = 0; it < 16; it++) {
        const int idx = tid + it * 256;          /* 0..4095 */
        const int kp = idx >> 6, d = idx & 63;
        float v0 = Vs[(size_t)(2 * kp) * D_ + d];
        float v1 = Vs[(size_t)(2 * kp + 1) * D_ + d];
        uint32_t h2, l2;
        bf16_split2(v0, v1, h2, l2);
        const int soff = (d * EV_STRIDE + 2 * kp) * 2;
        *(uint32_t*)(smx + SM_VTHI + soff) = h2;
        *(uint32_t*)(smx + SM_VTLO + soff) = l2;
    }
    __syncthreads();

    /* ================= QK^T: warp tile 32 x 64 ================= */
    float c[2][8][4];
#pragma unroll
    for (int t = 0; t < 2; t++)
#pragma unroll
        for (int j = 0; j < 8; j++)
#pragma unroll
            for (int r = 0; r < 4; r++) c[t][j][r] = 0.0f;

#pragma unroll
    for (int p = 0; p < 3; p++) {
        const char* Ab = smx + ((p == 2) ? SM_QLO : SM_QHI);
        const char* Bb = smx + ((p == 1) ? SM_KLO : SM_KHI);
#pragma unroll
        for (int ks = 0; ks < 4; ks++) {
            uint32_t a[2][4];
#pragma unroll
            for (int t = 0; t < 2; t++) {
                const int base = (32 * wr + 16 * t + g) * QK_STRIDE + 16 * ks + 2 * tg;
                a[t][0] = *(const uint32_t*)(Ab + 2 * base);
                a[t][1] = *(const uint32_t*)(Ab + 2 * (base + 8 * QK_STRIDE));
                a[t][2] = *(const uint32_t*)(Ab + 2 * (base + 8));
                a[t][3] = *(const uint32_t*)(Ab + 2 * (base + 8 * QK_STRIDE + 8));
            }
#pragma unroll
            for (int j = 0; j < 8; j++) {
                const int cb = (64 * wc + 8 * j + g) * QK_STRIDE + 16 * ks + 2 * tg;
                uint32_t b0 = *(const uint32_t*)(Bb + 2 * cb);
                uint32_t b1 = *(const uint32_t*)(Bb + 2 * (cb + 8));
                MMA16816(c[0][j], a[0], b0, b1);
                MMA16816(c[1][j], a[1], b0, b1);
            }
        }
    }
    __syncthreads();   /* all Q/K smem reads done; E may overwrite */

    /* ======== epilogue: mask+exp, E split to smem, row sums ======== */
    float rs[2][2] = {{0.0f, 0.0f}, {0.0f, 0.0f}};
#pragma unroll
    for (int t = 0; t < 2; t++) {
#pragma unroll
        for (int u = 0; u < 2; u++) {
            const int row = 32 * wr + 16 * t + 8 * u + g;
#pragma unroll
            for (int j = 0; j < 8; j++) {
                const int cb = 64 * wc + 8 * j + 2 * tg;
                float s0 = c[t][j][2 * u]     * 0.125f;
                float s1 = c[t][j][2 * u + 1] * 0.125f;
                float e0 = (diag && (cb     > row)) ? 0.0f : fast_exp(s0);
                float e1 = (diag && (cb + 1 > row)) ? 0.0f : fast_exp(s1);
                rs[t][u] += e0 + e1;
                uint32_t h2, l2;
                bf16_split2(e0, e1, h2, l2);
                const int eoff = (row * EV_STRIDE + cb) * 2;
                *(uint32_t*)(smx + SM_EHI + eoff) = h2;
                *(uint32_t*)(smx + SM_ELO + eoff) = l2;
            }
        }
    }
#pragma unroll
    for (int t = 0; t < 2; t++)
#pragma unroll
        for (int u = 0; u < 2; u++) {
            float v = rs[t][u];
            v += __shfl_xor_sync(0xffffffffu, v, 1);
            v += __shfl_xor_sync(0xffffffffu, v, 2);
            if (tg == 0) {
                const int row = 32 * wr + 16 * t + 8 * u + g;
                ((float*)(smx + SM_RSUM))[row * 2 + wc] = v;
            }
        }
    __syncthreads();

    if (tid < 128) {
        const float* r = (const float*)(smx + SM_RSUM);
        g_Lp[(size_t)unit * 128 + tid] = r[2 * tid] + r[2 * tid + 1];
    }

    /* ================= O = E @ V: warp tile 32 x 32 ================= */
    float o[2][4][4];
#pragma unroll
    for (int t = 0; t < 2; t++)
#pragma unroll
        for (int j = 0; j < 4; j++)
#pragma unroll
            for (int r = 0; r < 4; r++) o[t][j][r] = 0.0f;

#pragma unroll
    for (int p = 0; p < 3; p++) {
        const char* Ab = smx + ((p == 2) ? SM_ELO : SM_EHI);
        const char* Bb = smx + ((p == 1) ? SM_VTLO : SM_VTHI);
#pragma unroll
        for (int ks = 0; ks < 8; ks++) {
            uint32_t a[2][4];
#pragma unroll
            for (int t = 0; t < 2; t++) {
                const int base = (32 * wr + 16 * t + g) * EV_STRIDE + 16 * ks + 2 * tg;
                a[t][0] = *(const uint32_t*)(Ab + 2 * base);
                a[t][1] = *(const uint32_t*)(Ab + 2 * (base + 8 * EV_STRIDE));
                a[t][2] = *(const uint32_t*)(Ab + 2 * (base + 8));
                a[t][3] = *(const uint32_t*)(Ab + 2 * (base + 8 * EV_STRIDE + 8));
            }
#pragma unroll
            for (int j = 0; j < 4; j++) {
                const int cb = (32 * wc + 8 * j + g) * EV_STRIDE + 16 * ks + 2 * tg;
                uint32_t b0 = *(const uint32_t*)(Bb + 2 * cb);
                uint32_t b1 = *(const uint32_t*)(Bb + 2 * (cb + 8));
                MMA16816(o[0][j], a[0], b0, b1);
                MMA16816(o[1][j], a[1], b0, b1);
            }
        }
    }

    /* ---- coalesced W store: reconstruct e = hi + lo from E smem ---- */
    if (writeW) {
        float* Wt = outW + ((size_t)(b * S_ + qt * BQ)) * S_ + (size_t)kt * BK;
#pragma unroll
        for (int it = 0; it < 16; it++) {
            const int f   = tid + it * 256;      /* float4 id: 0..4095 */
            const int row = f >> 5, c4 = f & 31;
            const int eo  = (row * EV_STRIDE + 4 * c4) * 2;
            uint32_t h0 = *(const uint32_t*)(smx + SM_EHI + eo);
            uint32_t l0 = *(const uint32_t*)(smx + SM_ELO + eo);
            uint32_t h1 = *(const uint32_t*)(smx + SM_EHI + eo + 4);
            uint32_t l1 = *(const uint32_t*)(smx + SM_ELO + eo + 4);
            float4 w;
            w.x = __uint_as_float(h0 << 16)          + __uint_as_float(l0 << 16);
            w.y = __uint_as_float(h0 & 0xFFFF0000u)  + __uint_as_float(l0 & 0xFFFF0000u);
            w.z = __uint_as_float(h1 << 16)          + __uint_as_float(l1 << 16);
            w.w = __uint_as_float(h1 & 0xFFFF0000u)  + __uint_as_float(l1 & 0xFFFF0000u);
            *(float4*)(Wt + (size_t)row * S_ + 4 * c4) = w;
        }
    }

    /* ---- store O partials ---- */
    float* Ob = g_Op + (size_t)unit * (128 * 64);
#pragma unroll
    for (int t = 0; t < 2; t++)
#pragma unroll
        for (int u = 0; u < 2; u++) {
            const int row = 32 * wr + 16 * t + 8 * u + g;
#pragma unroll
            for (int j = 0; j < 4; j++) {
                const int cb = 32 * wc + 8 * j + 2 * tg;
                float2 w;
                w.x = o[t][j][2 * u];
                w.y = o[t][j][2 * u + 1];
                *(float2*)(Ob + (size_t)row * 64 + cb) = w;
            }
        }
}

/* ---------------- Kernel B1: invL per row ---------------- */
__global__ void __launch_bounds__(256)
reduce_l()
{
    int t = blockIdx.x * 256 + threadIdx.x;
    if (t >= B_ * S_) return;
    int b = t >> 12, q = t & (S_ - 1);
    int qt = q >> 7, i = q & 127;
    int tri = qt * (qt + 1) / 2;
    float s = 0.0f;
    for (int kt = 0; kt <= qt; kt++)
        s += g_Lp[((size_t)(b * UNITS_PER_B + tri + kt)) * 128 + i];
    g_invL[t] = 1.0f / s;
}

/* ---------------- Kernel B2: O = (sum of partials) * invL ---------------- */
__global__ void __launch_bounds__(256)
reduce_o(float* __restrict__ outV)
{
    int t = blockIdx.x * 256 + threadIdx.x;
    if (t >= B_ * S_ * (D_ / 4)) return;
    int d4 = t & 15;
    int q  = (t >> 4) & (S_ - 1);
    int b  = t >> 16;
    int qt = q >> 7, i = q & 127;
    int tri = qt * (qt + 1) / 2;
    float ax = 0.f, ay = 0.f, az = 0.f, aw = 0.f;
    for (int kt = 0; kt <= qt; kt++) {
        const float4 v = *(const float4*)(g_Op +
            ((size_t)(b * UNITS_PER_B + tri + kt) * 128 + i) * 64 + d4 * 4);
        ax += v.x; ay += v.y; az += v.z; aw += v.w;
    }
    float inv = g_invL[b * S_ + q];
    float4 r; r.x = ax * inv; r.y = ay * inv; r.z = az * inv; r.w = aw * inv;
    *(float4*)(outV + ((size_t)(b * S_ + q)) * D_ + d4 * 4) = r;
}

/* ---------------- Kernel C: normalize weights + zero upper tiles -------- */
__global__ void __launch_bounds__(256)
norm_w(float* __restrict__ outW)
{
    size_t t = (size_t)blockIdx.x * 256 + threadIdx.x;   /* float4 index */
    int kq = (int)(t & 1023);
    int q  = (int)((t >> 10) & (S_ - 1));
    int b  = (int)(t >> 22);
    float4* p = (float4*)outW + t;
    int k = kq * 4;
    if ((k >> 7) > (q >> 7)) {
        float4 z; z.x = z.y = z.z = z.w = 0.0f;
        *p = z;
    } else {
        float inv = g_invL[b * S_ + q];
        float4 v = *p;
        v.x *= inv; v.y *= inv; v.z *= inv; v.w *= inv;
        *p = v;
    }
}

/* ------------------------------------------------------------------ */
extern "C" void kernel_launch(void* const* d_in, const int* in_sizes, int n_in,
                              void* d_out, int out_size)
{
    const float* Q = (const float*)d_in[0];
    const float* K = (const float*)d_in[1];
    const float* V = (const float*)d_in[2];

    const long long VE = (long long)B_ * S_ * D_;
    const long long WE = (long long)B_ * S_ * S_;

    float* outVec = nullptr;
    float* outW   = nullptr;
    int writeW = 0;
    if ((long long)out_size == VE + WE) {
        outVec = (float*)d_out;
        outW   = (float*)d_out + VE;
        writeW = 1;
    } else if ((long long)out_size == WE) {
        outW   = (float*)d_out;
        writeW = 1;
    } else {
        outVec = (float*)d_out;
    }
    float* wPtr = writeW ? outW : (float*)d_out;

    cudaFuncSetAttribute(attn_tiles, cudaFuncAttributeMaxDynamicSharedMemorySize,
                         SMEM_TOTAL);

    dim3 gA(UNITS_PER_B, B_);
    attn_tiles<<<gA, 256, SMEM_TOTAL>>>(Q, K, V, wPtr, writeW);

    reduce_l<<<(B_ * S_ + 255) / 256, 256>>>();

    if (outVec)
        reduce_o<<<(B_ * S_ * (D_ / 4) + 255) / 256, 256>>>(outVec);

    if (writeW) {
        long long nf4 = WE / 4;
        norm_w<<<(unsigned)(nf4 / 256), 256>>>(outW);
    }
}